// round 8
// baseline (speedup 1.0000x reference)
#include <cuda_runtime.h>
#include <cuda_fp16.h>
#include <cstdint>

// ---------------------------------------------------------------------------
// VersorLinear (Cl(4,1), 32-dim) via the real-algebra isomorphism
// Cl(4,1) ~= M4(C):  y[b,o] = sum_f x[b,f] * w[o,f]  ==>
//   Yhat[b,o] = sum_f Xhat[b,f] . What[o,f]   (4x4 complex matrix products)
// One real GEMM  Y[16384,1024] = Xt[16384,1024] . Wt[1024,1024]
//   (complex realified: K=(f,s,{re,im}), N=(o,c,{re,im}) with the
//    [[Wr,Wi],[-Wi,Wr]] block structure)  -- 4x fewer MACs than the direct
// 4096^3 GEMM. Inverse transform y_i = 1/4 Re tr(R_i^dag Yhat) + L2 norm
// fused into the GEMM epilogue. Rep matrices built numerically on device
// from Dirac gammas (homomorphism => all Cayley signs automatic).
// fp16 m16n8k16 MMA, fp32 accum (proven ~94% tensor-active config).
// ---------------------------------------------------------------------------

#define MDIM 4096
#define GM 16384      // (b, r)    = 4096*4
#define GK 1024       // (f, s, p) = 128*4*2
#define GN 1024       // (o, c, q) = 128*4*2

__device__ __half g_Xt[(size_t)GM * GK];     // transformed x   [m][k]
__device__ __half g_Wt16[(size_t)GN * GK];   // transformed w   [n][k]
__device__ float  g_TF[32 * 32];   // forward:  [(r*8+s*2+p)][i] = part(R_i[r][s])
__device__ float  g_TI[32 * 32];   // inverse:  [i][(r*4+c)*2+q] = part(R_i[r][c])/4

struct cpx { float re, im; };
__device__ __forceinline__ cpx cmul(cpx a, cpx b) {
    return { a.re * b.re - a.im * b.im, a.re * b.im + a.im * b.re };
}

__device__ void mm4(cpx* out, const cpx* A, const cpx* B) {
    for (int r = 0; r < 4; r++)
        for (int c = 0; c < 4; c++) {
            cpx s = {0.f, 0.f};
            for (int k = 0; k < 4; k++) {
                cpx p = cmul(A[r * 4 + k], B[k * 4 + c]);
                s.re += p.re; s.im += p.im;
            }
            out[r * 4 + c] = s;
        }
}

// Build rep matrices R_a = ordered product of gammas, fill g_TF / g_TI.
__global__ void build_tables() {
    if (threadIdx.x != 0 || blockIdx.x != 0) return;
    cpx G[5][16];
    for (int m = 0; m < 5; m++)
        for (int e = 0; e < 16; e++) G[m][e] = {0.f, 0.f};
    // e0 = beta = diag(1,1,-1,-1)
    G[0][0] = {1,0}; G[0][5] = {1,0}; G[0][10] = {-1,0}; G[0][15] = {-1,0};
    // e1 = alpha1 ([[0,s1],[s1,0]], s1=[[0,1],[1,0]])
    G[1][3] = {1,0}; G[1][6] = {1,0}; G[1][9] = {1,0}; G[1][12] = {1,0};
    // e2 = alpha2 (s2=[[0,-i],[i,0]])
    G[2][3] = {0,-1}; G[2][6] = {0,1}; G[2][9] = {0,-1}; G[2][12] = {0,1};
    // e3 = alpha3 (s3=[[1,0],[0,-1]])
    G[3][2] = {1,0}; G[3][7] = {-1,0}; G[3][8] = {1,0}; G[3][13] = {-1,0};
    // e4 = i * e0*e1*e2*e3   (squares to -1, anticommutes with e0..e3)
    {
        cpx P[16], Q[16], T[16];
        mm4(P, G[0], G[1]);
        mm4(Q, G[2], G[3]);
        mm4(T, P, Q);
        for (int e = 0; e < 16; e++) G[4][e] = { -T[e].im, T[e].re };  // *i
    }
    // R_a = prod_{i ascending, bit i of a} G[i]
    for (int a = 0; a < 32; a++) {
        cpx R[16], T[16];
        for (int e = 0; e < 16; e++) R[e] = {0.f, 0.f};
        R[0] = R[5] = R[10] = R[15] = {1.f, 0.f};
        for (int i = 0; i < 5; i++) {
            if ((a >> i) & 1) {
                mm4(T, R, G[i]);
                for (int e = 0; e < 16; e++) R[e] = T[e];
            }
        }
        for (int r = 0; r < 4; r++)
            for (int c = 0; c < 4; c++) {
                cpx v = R[r * 4 + c];
                g_TF[(r * 8 + c * 2 + 0) * 32 + a] = v.re;   // (r, s=c, p)
                g_TF[(r * 8 + c * 2 + 1) * 32 + a] = v.im;
                g_TI[a * 32 + (r * 4 + c) * 2 + 0] = 0.25f * v.re;
                g_TI[a * 32 + (r * 4 + c) * 2 + 1] = 0.25f * v.im;
            }
    }
}

// x[b,f,0..31] -> Xhat[b,f] (4x4 complex) -> g_Xt rows m=b*4+r, cols f*8+(s*2+p)
__global__ void xform_x(const float* __restrict__ X) {
    int t = blockIdx.x * blockDim.x + threadIdx.x;   // 0 .. 524287
    int b = t >> 7, f = t & 127;
    const float* xv = X + (size_t)b * 4096 + f * 32;
    float xr[32];
#pragma unroll 8
    for (int i = 0; i < 32; i++) xr[i] = xv[i];
    __half out[32];
#pragma unroll
    for (int e = 0; e < 32; e++) {        // e = r*8 + s*2 + p
        float a = 0.f;
#pragma unroll 8
        for (int i = 0; i < 32; i++) a += g_TF[e * 32 + i] * xr[i];
        out[e] = __float2half_rn(a);
    }
#pragma unroll
    for (int r = 0; r < 4; r++) {
        size_t off = ((size_t)(b * 4 + r)) * GK + f * 8;
        *reinterpret_cast<uint4*>(&g_Xt[off]) =
            *reinterpret_cast<const uint4*>(&out[r * 8]);
    }
}

// w[o,f,0..31] -> What[o,f] -> g_Wt16[n=o*8+c*2+q][k=f*8+s*2+p] (block-realified)
__global__ void xform_w(const float* __restrict__ W) {
    int t = blockIdx.x * blockDim.x + threadIdx.x;   // 0 .. 16383
    int o = t >> 7, f = t & 127;
    const float* wv = W + (size_t)o * 4096 + f * 32;
    float wr32[32];
#pragma unroll 8
    for (int j = 0; j < 32; j++) wr32[j] = wv[j];
#pragma unroll
    for (int s = 0; s < 4; s++)
#pragma unroll
        for (int c = 0; c < 4; c++) {
            float wr = 0.f, wi = 0.f;
#pragma unroll 8
            for (int j = 0; j < 32; j++) {
                wr += g_TF[(s * 8 + c * 2 + 0) * 32 + j] * wr32[j];
                wi += g_TF[(s * 8 + c * 2 + 1) * 32 + j] * wr32[j];
            }
            int kx = f * 8 + s * 2;
            int n0 = o * 8 + c * 2;
            g_Wt16[(size_t)(n0 + 0) * GK + kx + 0] = __float2half_rn(wr);
            g_Wt16[(size_t)(n0 + 0) * GK + kx + 1] = __float2half_rn(-wi);
            g_Wt16[(size_t)(n0 + 1) * GK + kx + 0] = __float2half_rn(wi);
            g_Wt16[(size_t)(n0 + 1) * GK + kx + 1] = __float2half_rn(wr);
        }
}

// ---------------------------------------------------------------------------
#define BM 128
#define BN 128
#define BK 32
#define NST 4
#define LDSD 40                          // smem row stride in HALFS
#define STG_H (BM * LDSD)                // 5120 halfs per stage per matrix
#define SMEM_BYTES 81920                 // NST*2*STG_H*2; epilogue fits inside

#define CP_ASYNC16(smaddr, gptr) \
    asm volatile("cp.async.cg.shared.global [%0], [%1], 16;" :: "r"(smaddr), "l"(gptr))

__global__ __launch_bounds__(256, 2)
void gemm_tc_kernel(float* __restrict__ C) {
    extern __shared__ __half smem[];
    __half* As = smem;                    // [NST][BM][LDSD]
    __half* Bs = smem + NST * STG_H;
    uint32_t sAs = (uint32_t)__cvta_generic_to_shared(As);
    uint32_t sBs = (uint32_t)__cvta_generic_to_shared(Bs);

    const int tid  = threadIdx.x;
    const int lane = tid & 31;
    const int wid  = tid >> 5;
    const int warpM = wid >> 2;          // 0..1
    const int warpN = wid & 3;           // 0..3
    const int blockRow = blockIdx.y * BM;
    const int blockCol = blockIdx.x * BN;

    const int r0 = tid >> 2;             // 0..63
    const int c8 = (tid & 3) * 8;
    const __half* gA = g_Xt   + (size_t)(blockRow + r0) * GK + c8;
    const __half* gB = g_Wt16 + (size_t)(blockCol + r0) * GK + c8;

#define LOAD_TILE(t, stage) do {                                               \
    const __half* _ga = gA + (size_t)(t) * BK;                                 \
    const __half* _gb = gB + (size_t)(t) * BK;                                 \
    uint32_t _sa = sAs + (uint32_t)((stage) * STG_H + r0 * LDSD + c8) * 2u;    \
    uint32_t _sb = sBs + (uint32_t)((stage) * STG_H + r0 * LDSD + c8) * 2u;    \
    CP_ASYNC16(_sa,                 _ga);                                      \
    CP_ASYNC16(_sa + 64 * LDSD * 2, _ga + (size_t)64 * GK);                    \
    CP_ASYNC16(_sb,                 _gb);                                      \
    CP_ASYNC16(_sb + 64 * LDSD * 2, _gb + (size_t)64 * GK);                    \
    asm volatile("cp.async.commit_group;");                                    \
} while (0)

    float acc[4][4][4] = {};

    LOAD_TILE(0, 0);
    LOAD_TILE(1, 1);
    LOAD_TILE(2, 2);

    const int aRowBase = warpM * 64 + (lane >> 2);
    const int t2 = (lane & 3) * 2;
    const int bRowBase = warpN * 32 + (lane >> 2);

    const int T = GK / BK;               // 32
    for (int t = 0; t < T; t++) {
        const int stage = t & (NST - 1);
        if (t < T - 1) asm volatile("cp.async.wait_group 2;");
        else           asm volatile("cp.async.wait_group 0;");
        __syncthreads();
        if (t + 3 < T) LOAD_TILE(t + 3, (t + 3) & (NST - 1));

        const __half* as = As + stage * STG_H + aRowBase * LDSD + t2;
        const __half* bs = Bs + stage * STG_H + bRowBase * LDSD + t2;

#pragma unroll
        for (int ks = 0; ks < 2; ks++) {
            const int kof = ks * 16;
            uint32_t a[4][4], b[4][2];
#pragma unroll
            for (int mf = 0; mf < 4; mf++) {
                a[mf][0] = *reinterpret_cast<const uint32_t*>(&as[(mf * 16    ) * LDSD + kof    ]);
                a[mf][1] = *reinterpret_cast<const uint32_t*>(&as[(mf * 16 + 8) * LDSD + kof    ]);
                a[mf][2] = *reinterpret_cast<const uint32_t*>(&as[(mf * 16    ) * LDSD + kof + 8]);
                a[mf][3] = *reinterpret_cast<const uint32_t*>(&as[(mf * 16 + 8) * LDSD + kof + 8]);
            }
#pragma unroll
            for (int nf = 0; nf < 4; nf++) {
                b[nf][0] = *reinterpret_cast<const uint32_t*>(&bs[(nf * 8) * LDSD + kof    ]);
                b[nf][1] = *reinterpret_cast<const uint32_t*>(&bs[(nf * 8) * LDSD + kof + 8]);
            }
#pragma unroll
            for (int mf = 0; mf < 4; mf++)
#pragma unroll
                for (int nf = 0; nf < 4; nf++)
                    asm volatile(
                        "mma.sync.aligned.m16n8k16.row.col.f32.f16.f16.f32 "
                        "{%0,%1,%2,%3}, {%4,%5,%6,%7}, {%8,%9}, {%0,%1,%2,%3};"
                        : "+f"(acc[mf][nf][0]), "+f"(acc[mf][nf][1]),
                          "+f"(acc[mf][nf][2]), "+f"(acc[mf][nf][3])
                        : "r"(a[mf][0]), "r"(a[mf][1]), "r"(a[mf][2]), "r"(a[mf][3]),
                          "r"(b[nf][0]), "r"(b[nf][1]));
        }
    }

    // ---- fused epilogue: stage -> inverse transform -> normalize -> store --
    // Tile holds 512 complete multivectors: b_l in [0,32), o_l in [0,16).
    // Stage layout (transposed): S[e][g], e=(r*8 + (n&7)) in [0,32),
    // g = b_l*16 + o_l in [0,512), row stride 520 (conflict-free gathers).
    float* S   = reinterpret_cast<float*>(smem);       // 32*520 floats
    float* TIs = S + 32 * 520;                         // 1024 floats
    __syncthreads();   // all mainloop smem reads complete before overwrite

    for (int idx = tid; idx < 1024; idx += 256) TIs[idx] = g_TI[idx];

#pragma unroll
    for (int mf = 0; mf < 4; mf++)
#pragma unroll
        for (int nf = 0; nf < 4; nf++)
#pragma unroll
            for (int cc = 0; cc < 4; cc++) {
                int ml = warpM * 64 + mf * 16 + (lane >> 2) + ((cc >> 1) ? 8 : 0);
                int nl = warpN * 32 + nf * 8 + (lane & 3) * 2 + (cc & 1);
                int e = (ml & 3) * 8 + (nl & 7);
                int g = (ml >> 2) * 16 + (nl >> 3);
                S[e * 520 + g] = acc[mf][nf][cc];
            }
    __syncthreads();

    for (int g = tid; g < 512; g += 256) {
        int b_l = g >> 4, o_l = g & 15;
        float v[32];
#pragma unroll
        for (int e = 0; e < 32; e++) v[e] = S[e * 520 + g];
        float yv[32];
        float ss = 0.f;
#pragma unroll
        for (int i = 0; i < 32; i++) {
            float a = 0.f;
#pragma unroll
            for (int e = 0; e < 32; e++) a += TIs[i * 32 + e] * v[e];
            yv[i] = a;
            ss += a * a;
        }
        float inv = rsqrtf(ss + 1e-6f);
        size_t off = ((size_t)(blockIdx.y * 32 + b_l)) * 4096
                   + (size_t)(blockIdx.x * 16 + o_l) * 32;
#pragma unroll
        for (int i4 = 0; i4 < 8; i4++) {
            float4 o4 = make_float4(yv[i4 * 4 + 0] * inv, yv[i4 * 4 + 1] * inv,
                                    yv[i4 * 4 + 2] * inv, yv[i4 * 4 + 3] * inv);
            *reinterpret_cast<float4*>(C + off + i4 * 4) = o4;
        }
    }
}

// ---------------------------------------------------------------------------
extern "C" void kernel_launch(void* const* d_in, const int* in_sizes, int n_in,
                              void* d_out, int out_size) {
    const float* x = (const float*)d_in[0];
    const float* w = (const float*)d_in[1];
    if (n_in >= 2 && in_sizes[0] == 524288 && in_sizes[1] == 16777216) {
        const float* t = x; x = w; w = t;  // defensive order swap
    }
    float* y = (float*)d_out;

    build_tables<<<1, 1>>>();
    xform_x<<<2048, 256>>>(x);    // 524288 threads: one (b,f) each
    xform_w<<<64, 256>>>(w);      // 16384 threads: one (o,f) each

    cudaFuncSetAttribute(gemm_tc_kernel,
                         cudaFuncAttributeMaxDynamicSharedMemorySize, SMEM_BYTES);
    dim3 grid(GN / BN, GM / BM);  // 8 x 128
    gemm_tc_kernel<<<grid, 256, SMEM_BYTES>>>(y);
}

// round 10
// speedup vs baseline: 1.2209x; 1.2209x over previous
#include <cuda_runtime.h>
#include <cuda_fp16.h>
#include <cstdint>

// ---------------------------------------------------------------------------
// VersorLinear (Cl(4,1), 32-dim) via Cl(4,1) ~= M4(C):
//   Yhat[b,o] = sum_f Xhat[b,f] . What[o,f]  -> one real GEMM
//   [16384 x 1024 x 1024]  (4x fewer MACs than the direct 4096^3 GEMM).
// Round 10: round-9 design with the A-tile loader overflow FIXED
// (A tile = 1024 16B chunks, not 2048 — the extra 1024 were clobbering the
// next pipeline stage and the B region, hence round-9's rel_err=1.4).
// K-slab layouts (fully contiguous BK=64 tile loads), smem-staged transform
// tables, fp16 m16n8k16 MMA fp32 accum, validated fused inverse-transform +
// L2-norm epilogue.
// ---------------------------------------------------------------------------

#define MDIM 4096
#define GM 16384      // (b, r)    = 4096*4
#define GK 1024       // (f, s, p) = 128*4*2
#define GN 1024       // (o, c, q) = 128*4*2
#define BKH 64        // k-tile in halfs (one slab column block)
#define KT (GK / BKH) // 16 slabs

#define SLAB_A ((size_t)GM * BKH)    // halfs per A slab (1,048,576)
#define SLAB_B ((size_t)GN * BKH)    // halfs per B slab (65,536)

// Slab layouts: addr(m,k) = (k>>6)*SLAB + m*64 + (k&63)
__device__ __half g_Xt[(size_t)GM * GK];
__device__ __half g_Wt16[(size_t)GN * GK];
__device__ float  g_TF[32 * 32];   // [(r*8+s*2+p)][i] = part(R_i[r][s])
__device__ float  g_TI[32 * 32];   // [i][(r*4+c)*2+q] = part(R_i[r][c])/4

struct cpx { float re, im; };
__device__ __forceinline__ cpx cmul(cpx a, cpx b) {
    return { a.re * b.re - a.im * b.im, a.re * b.im + a.im * b.re };
}
__device__ void mm4(cpx* out, const cpx* A, const cpx* B) {
    for (int r = 0; r < 4; r++)
        for (int c = 0; c < 4; c++) {
            cpx s = {0.f, 0.f};
            for (int k = 0; k < 4; k++) {
                cpx p = cmul(A[r * 4 + k], B[k * 4 + c]);
                s.re += p.re; s.im += p.im;
            }
            out[r * 4 + c] = s;
        }
}

// Build rep matrices R_a = ordered gamma products; fill g_TF / g_TI.
__global__ void build_tables() {
    if (threadIdx.x != 0 || blockIdx.x != 0) return;
    cpx G[5][16];
    for (int m = 0; m < 5; m++)
        for (int e = 0; e < 16; e++) G[m][e] = {0.f, 0.f};
    G[0][0] = {1,0}; G[0][5] = {1,0}; G[0][10] = {-1,0}; G[0][15] = {-1,0};
    G[1][3] = {1,0}; G[1][6] = {1,0}; G[1][9] = {1,0}; G[1][12] = {1,0};
    G[2][3] = {0,-1}; G[2][6] = {0,1}; G[2][9] = {0,-1}; G[2][12] = {0,1};
    G[3][2] = {1,0}; G[3][7] = {-1,0}; G[3][8] = {1,0}; G[3][13] = {-1,0};
    {   // e4 = i * e0 e1 e2 e3
        cpx P[16], Q[16], T[16];
        mm4(P, G[0], G[1]);
        mm4(Q, G[2], G[3]);
        mm4(T, P, Q);
        for (int e = 0; e < 16; e++) G[4][e] = { -T[e].im, T[e].re };
    }
    for (int a = 0; a < 32; a++) {
        cpx R[16], T[16];
        for (int e = 0; e < 16; e++) R[e] = {0.f, 0.f};
        R[0] = R[5] = R[10] = R[15] = {1.f, 0.f};
        for (int i = 0; i < 5; i++)
            if ((a >> i) & 1) {
                mm4(T, R, G[i]);
                for (int e = 0; e < 16; e++) R[e] = T[e];
            }
        for (int r = 0; r < 4; r++)
            for (int c = 0; c < 4; c++) {
                cpx v = R[r * 4 + c];
                g_TF[(r * 8 + c * 2 + 0) * 32 + a] = v.re;
                g_TF[(r * 8 + c * 2 + 1) * 32 + a] = v.im;
                g_TI[a * 32 + (r * 4 + c) * 2 + 0] = 0.25f * v.re;
                g_TI[a * 32 + (r * 4 + c) * 2 + 1] = 0.25f * v.im;
            }
    }
}

// x[b,f,:] -> Xhat rows m=b*4+r written into slab layout.
__global__ void xform_x(const float* __restrict__ X) {
    __shared__ float TFs[1024];
    for (int i = threadIdx.x; i < 1024; i += 256) TFs[i] = g_TF[i];
    __syncthreads();

    int t = blockIdx.x * 256 + threadIdx.x;   // 0 .. 524287
    int b = t >> 7, f = t & 127;
    const float* xv = X + (size_t)b * 4096 + f * 32;
    float xr[32];
#pragma unroll
    for (int q = 0; q < 8; q++) {
        float4 v = *reinterpret_cast<const float4*>(xv + q * 4);
        xr[q * 4 + 0] = v.x; xr[q * 4 + 1] = v.y;
        xr[q * 4 + 2] = v.z; xr[q * 4 + 3] = v.w;
    }
    int kt = f >> 3, kk0 = (f & 7) * 8;
#pragma unroll
    for (int r = 0; r < 4; r++) {
        __half out[8];
#pragma unroll
        for (int sp = 0; sp < 8; sp++) {
            const float* row = &TFs[(r * 8 + sp) * 32];
            float a = 0.f;
#pragma unroll
            for (int i = 0; i < 32; i++) a += row[i] * xr[i];
            out[sp] = __float2half_rn(a);
        }
        size_t off = (size_t)kt * SLAB_A + (size_t)(b * 4 + r) * BKH + kk0;
        *reinterpret_cast<uint4*>(&g_Xt[off]) = *reinterpret_cast<const uint4*>(out);
    }
}

// w[o,f,:] -> What, realified [[Wr,Wi],[-Wi,Wr]], into slab layout.
__global__ void xform_w(const float* __restrict__ W) {
    __shared__ float TFs[1024];
    for (int i = threadIdx.x; i < 1024; i += 256) TFs[i] = g_TF[i];
    __syncthreads();

    int t = blockIdx.x * 256 + threadIdx.x;   // 0 .. 16383
    int o = t >> 7, f = t & 127;
    const float* wv = W + (size_t)o * 4096 + f * 32;
    float wr32[32];
#pragma unroll
    for (int q = 0; q < 8; q++) {
        float4 v = *reinterpret_cast<const float4*>(wv + q * 4);
        wr32[q * 4 + 0] = v.x; wr32[q * 4 + 1] = v.y;
        wr32[q * 4 + 2] = v.z; wr32[q * 4 + 3] = v.w;
    }
    int kt = f >> 3, kk0 = (f & 7) * 8;
#pragma unroll
    for (int s = 0; s < 4; s++)
#pragma unroll
        for (int c = 0; c < 4; c++) {
            float wr = 0.f, wi = 0.f;
#pragma unroll
            for (int j = 0; j < 32; j++) {
                wr += TFs[(s * 8 + c * 2 + 0) * 32 + j] * wr32[j];
                wi += TFs[(s * 8 + c * 2 + 1) * 32 + j] * wr32[j];
            }
            int kk = kk0 + s * 2;
            int n0 = o * 8 + c * 2;
            size_t base = (size_t)kt * SLAB_B;
            g_Wt16[base + (size_t)(n0 + 0) * BKH + kk + 0] = __float2half_rn(wr);
            g_Wt16[base + (size_t)(n0 + 0) * BKH + kk + 1] = __float2half_rn(-wi);
            g_Wt16[base + (size_t)(n0 + 1) * BKH + kk + 0] = __float2half_rn(wi);
            g_Wt16[base + (size_t)(n0 + 1) * BKH + kk + 1] = __float2half_rn(wr);
        }
}

// ---------------------------------------------------------------------------
#define BM 128
#define BN 128
#define NST 3
#define LDSD 72                          // smem row stride in HALFS (144 B)
#define STG_H (BM * LDSD)                // 9216 halfs per stage per matrix
#define SMEM_BYTES (NST * 2 * STG_H * 2) // 110592

#define CP_ASYNC16(smaddr, gptr) \
    asm volatile("cp.async.cg.shared.global [%0], [%1], 16;" :: "r"(smaddr), "l"(gptr))

__global__ __launch_bounds__(256, 2)
void gemm_tc_kernel(float* __restrict__ C) {
    extern __shared__ __half smem[];
    __half* As = smem;                    // [NST][BM][LDSD]
    __half* Bs = smem + NST * STG_H;
    uint32_t sAs = (uint32_t)__cvta_generic_to_shared(As);
    uint32_t sBs = (uint32_t)__cvta_generic_to_shared(Bs);

    const int tid  = threadIdx.x;
    const int lane = tid & 31;
    const int wid  = tid >> 5;
    const int warpM = wid >> 2;          // 0..1
    const int warpN = wid & 3;           // 0..3
    const int blockRow = blockIdx.y * BM;
    const int blockCol = blockIdx.x * BN;

    // Contiguous tile loads: A tile = 128 rows * 64 halfs = 16 KB = 1024
    // 16B chunks; B tile identical. 4 chunks per thread each.
#define LOAD_TILE(t, stage) do {                                               \
    const __half* _ga = g_Xt   + (size_t)(t) * SLAB_A + (size_t)blockRow * BKH;\
    const __half* _gb = g_Wt16 + (size_t)(t) * SLAB_B + (size_t)blockCol * BKH;\
    uint32_t _sa = sAs + (uint32_t)((stage) * STG_H) * 2u;                     \
    uint32_t _sb = sBs + (uint32_t)((stage) * STG_H) * 2u;                     \
    _Pragma("unroll")                                                          \
    for (int _i = 0; _i < 4; _i++) {                                           \
        int _j = tid + 256 * _i;                                               \
        CP_ASYNC16(_sa + (uint32_t)(((_j >> 3) * LDSD + (_j & 7) * 8) * 2),    \
                   _ga + (size_t)_j * 8);                                      \
    }                                                                          \
    _Pragma("unroll")                                                          \
    for (int _i = 0; _i < 4; _i++) {                                           \
        int _j = tid + 256 * _i;                                               \
        CP_ASYNC16(_sb + (uint32_t)(((_j >> 3) * LDSD + (_j & 7) * 8) * 2),    \
                   _gb + (size_t)_j * 8);                                      \
    }                                                                          \
    asm volatile("cp.async.commit_group;");                                    \
} while (0)

    float acc[4][4][4] = {};

    LOAD_TILE(0, 0);
    LOAD_TILE(1, 1);

    const int aRowBase = warpM * 64 + (lane >> 2);
    const int t2 = (lane & 3) * 2;
    const int bRowBase = warpN * 32 + (lane >> 2);

    for (int t = 0; t < KT; t++) {       // 16 iterations
        const int stage = t % NST;
        if (t < KT - 1) asm volatile("cp.async.wait_group 1;");
        else            asm volatile("cp.async.wait_group 0;");
        __syncthreads();
        if (t + 2 < KT) LOAD_TILE(t + 2, (t + 2) % NST);

        const __half* as = As + stage * STG_H + aRowBase * LDSD + t2;
        const __half* bs = Bs + stage * STG_H + bRowBase * LDSD + t2;

#pragma unroll
        for (int ks = 0; ks < 4; ks++) {             // four k16 slices in BK=64
            const int kof = ks * 16;
            uint32_t a[4][4], b[4][2];
#pragma unroll
            for (int mf = 0; mf < 4; mf++) {
                a[mf][0] = *reinterpret_cast<const uint32_t*>(&as[(mf * 16    ) * LDSD + kof    ]);
                a[mf][1] = *reinterpret_cast<const uint32_t*>(&as[(mf * 16 + 8) * LDSD + kof    ]);
                a[mf][2] = *reinterpret_cast<const uint32_t*>(&as[(mf * 16    ) * LDSD + kof + 8]);
                a[mf][3] = *reinterpret_cast<const uint32_t*>(&as[(mf * 16 + 8) * LDSD + kof + 8]);
            }
#pragma unroll
            for (int nf = 0; nf < 4; nf++) {
                b[nf][0] = *reinterpret_cast<const uint32_t*>(&bs[(nf * 8) * LDSD + kof    ]);
                b[nf][1] = *reinterpret_cast<const uint32_t*>(&bs[(nf * 8) * LDSD + kof + 8]);
            }
#pragma unroll
            for (int mf = 0; mf < 4; mf++)
#pragma unroll
                for (int nf = 0; nf < 4; nf++)
                    asm volatile(
                        "mma.sync.aligned.m16n8k16.row.col.f32.f16.f16.f32 "
                        "{%0,%1,%2,%3}, {%4,%5,%6,%7}, {%8,%9}, {%0,%1,%2,%3};"
                        : "+f"(acc[mf][nf][0]), "+f"(acc[mf][nf][1]),
                          "+f"(acc[mf][nf][2]), "+f"(acc[mf][nf][3])
                        : "r"(a[mf][0]), "r"(a[mf][1]), "r"(a[mf][2]), "r"(a[mf][3]),
                          "r"(b[nf][0]), "r"(b[nf][1]));
        }
    }

    // ---- fused epilogue (validated in round 8): inverse transform + norm ---
    float* S   = reinterpret_cast<float*>(smem);       // [32][520]
    float* TIs = S + 32 * 520;                         // 1024 floats
    __syncthreads();

    for (int idx = tid; idx < 1024; idx += 256) TIs[idx] = g_TI[idx];

#pragma unroll
    for (int mf = 0; mf < 4; mf++)
#pragma unroll
        for (int nf = 0; nf < 4; nf++)
#pragma unroll
            for (int cc = 0; cc < 4; cc++) {
                int ml = warpM * 64 + mf * 16 + (lane >> 2) + ((cc >> 1) ? 8 : 0);
                int nl = warpN * 32 + nf * 8 + (lane & 3) * 2 + (cc & 1);
                int e = (ml & 3) * 8 + (nl & 7);
                int g = (ml >> 2) * 16 + (nl >> 3);
                S[e * 520 + g] = acc[mf][nf][cc];
            }
    __syncthreads();

    for (int g = tid; g < 512; g += 256) {
        int b_l = g >> 4, o_l = g & 15;
        float v[32];
#pragma unroll
        for (int e = 0; e < 32; e++) v[e] = S[e * 520 + g];
        float yv[32];
        float ss = 0.f;
#pragma unroll
        for (int i = 0; i < 32; i++) {
            float a = 0.f;
#pragma unroll
            for (int e = 0; e < 32; e++) a += TIs[i * 32 + e] * v[e];
            yv[i] = a;
            ss += a * a;
        }
        float inv = rsqrtf(ss + 1e-6f);
        size_t off = ((size_t)(blockIdx.y * 32 + b_l)) * 4096
                   + (size_t)(blockIdx.x * 16 + o_l) * 32;
#pragma unroll
        for (int i4 = 0; i4 < 8; i4++) {
            float4 o4 = make_float4(yv[i4 * 4 + 0] * inv, yv[i4 * 4 + 1] * inv,
                                    yv[i4 * 4 + 2] * inv, yv[i4 * 4 + 3] * inv);
            *reinterpret_cast<float4*>(C + off + i4 * 4) = o4;
        }
    }
}

// ---------------------------------------------------------------------------
extern "C" void kernel_launch(void* const* d_in, const int* in_sizes, int n_in,
                              void* d_out, int out_size) {
    const float* x = (const float*)d_in[0];
    const float* w = (const float*)d_in[1];
    if (n_in >= 2 && in_sizes[0] == 524288 && in_sizes[1] == 16777216) {
        const float* t = x; x = w; w = t;  // defensive order swap
    }
    float* y = (float*)d_out;

    build_tables<<<1, 1>>>();
    xform_x<<<2048, 256>>>(x);
    xform_w<<<64, 256>>>(w);

    cudaFuncSetAttribute(gemm_tc_kernel,
                         cudaFuncAttributeMaxDynamicSharedMemorySize, SMEM_BYTES);
    dim3 grid(GN / BN, GM / BM);  // 8 x 128
    gemm_tc_kernel<<<grid, 256, SMEM_BYTES>>>(y);
}

// round 12
// speedup vs baseline: 1.5254x; 1.2493x over previous
#include <cuda_runtime.h>
#include <cuda_fp16.h>
#include <cstdint>

// ---------------------------------------------------------------------------
// VersorLinear (Cl(4,1), 32-dim) via Cl(4,1) ~= M4(C):
//   Yhat[b,o] = sum_f Xhat[b,f] . What[o,f]  -> one real GEMM
//   [16384 x 1024 x 1024]  (4x fewer MACs than the direct 4096^3 GEMM).
// Round 11: SPILL-FREE fused epilogue. Rounds 8/10 were killed by ptxas
// spilling the epilogue's v[32]/yv[32] arrays to local memory at the
// 128-reg __launch_bounds__ cap (~2 GB of DRAM-backed local traffic ==
// the observed DRAM=45% / tensor=7.5% profile). New epilogue:
//   - norm via TI orthogonality: sum_i y_i^2 = 1/4 sum_e v_e^2
//   - outputs streamed one scalar accumulator at a time (no arrays)
// Mainloop identical to round 10 (passed, rel_err 2.98e-4).
// ---------------------------------------------------------------------------

#define MDIM 4096
#define GM 16384      // (b, r)    = 4096*4
#define GK 1024       // (f, s, p) = 128*4*2
#define GN 1024       // (o, c, q) = 128*4*2
#define BKH 64        // k-tile in halfs (one slab column block)
#define KT (GK / BKH) // 16 slabs

#define SLAB_A ((size_t)GM * BKH)    // halfs per A slab
#define SLAB_B ((size_t)GN * BKH)

// Slab layouts: addr(m,k) = (k>>6)*SLAB + m*64 + (k&63)
__device__ __half g_Xt[(size_t)GM * GK];
__device__ __half g_Wt16[(size_t)GN * GK];
__device__ float  g_TF[32 * 32];   // [(r*8+s*2+p)][i] = part(R_i[r][s])
__device__ float  g_TI[32 * 32];   // [i][(r*4+c)*2+q] = part(R_i[r][c])/4

struct cpx { float re, im; };
__device__ __forceinline__ cpx cmul(cpx a, cpx b) {
    return { a.re * b.re - a.im * b.im, a.re * b.im + a.im * b.re };
}
__device__ void mm4(cpx* out, const cpx* A, const cpx* B) {
    for (int r = 0; r < 4; r++)
        for (int c = 0; c < 4; c++) {
            cpx s = {0.f, 0.f};
            for (int k = 0; k < 4; k++) {
                cpx p = cmul(A[r * 4 + k], B[k * 4 + c]);
                s.re += p.re; s.im += p.im;
            }
            out[r * 4 + c] = s;
        }
}

// One thread per blade a (32 threads): R_a = ordered gamma product.
__global__ void build_tables() {
    int a = threadIdx.x;
    if (a >= 32) return;
    cpx G[5][16];
    for (int m = 0; m < 5; m++)
        for (int e = 0; e < 16; e++) G[m][e] = {0.f, 0.f};
    G[0][0] = {1,0}; G[0][5] = {1,0}; G[0][10] = {-1,0}; G[0][15] = {-1,0};
    G[1][3] = {1,0}; G[1][6] = {1,0}; G[1][9] = {1,0}; G[1][12] = {1,0};
    G[2][3] = {0,-1}; G[2][6] = {0,1}; G[2][9] = {0,-1}; G[2][12] = {0,1};
    G[3][2] = {1,0}; G[3][7] = {-1,0}; G[3][8] = {1,0}; G[3][13] = {-1,0};
    {   // e4 = i * e0 e1 e2 e3
        cpx P[16], Q[16], T[16];
        mm4(P, G[0], G[1]);
        mm4(Q, G[2], G[3]);
        mm4(T, P, Q);
        for (int e = 0; e < 16; e++) G[4][e] = { -T[e].im, T[e].re };
    }
    cpx R[16], T[16];
    for (int e = 0; e < 16; e++) R[e] = {0.f, 0.f};
    R[0] = R[5] = R[10] = R[15] = {1.f, 0.f};
    for (int i = 0; i < 5; i++)
        if ((a >> i) & 1) {
            mm4(T, R, G[i]);
            for (int e = 0; e < 16; e++) R[e] = T[e];
        }
    for (int r = 0; r < 4; r++)
        for (int c = 0; c < 4; c++) {
            cpx v = R[r * 4 + c];
            g_TF[(r * 8 + c * 2 + 0) * 32 + a] = v.re;
            g_TF[(r * 8 + c * 2 + 1) * 32 + a] = v.im;
            g_TI[a * 32 + (r * 4 + c) * 2 + 0] = 0.25f * v.re;
            g_TI[a * 32 + (r * 4 + c) * 2 + 1] = 0.25f * v.im;
        }
}

// x[b,f,:] -> Xhat rows m=b*4+r written into slab layout.
__global__ void xform_x(const float* __restrict__ X) {
    __shared__ float TFs[1024];
    for (int i = threadIdx.x; i < 1024; i += 256) TFs[i] = g_TF[i];
    __syncthreads();

    int t = blockIdx.x * 256 + threadIdx.x;   // 0 .. 524287
    int b = t >> 7, f = t & 127;
    const float* xv = X + (size_t)b * 4096 + f * 32;
    float xr[32];
#pragma unroll
    for (int q = 0; q < 8; q++) {
        float4 v = *reinterpret_cast<const float4*>(xv + q * 4);
        xr[q * 4 + 0] = v.x; xr[q * 4 + 1] = v.y;
        xr[q * 4 + 2] = v.z; xr[q * 4 + 3] = v.w;
    }
    int kt = f >> 3, kk0 = (f & 7) * 8;
#pragma unroll
    for (int r = 0; r < 4; r++) {
        __half out[8];
#pragma unroll
        for (int sp = 0; sp < 8; sp++) {
            const float* row = &TFs[(r * 8 + sp) * 32];
            float a = 0.f;
#pragma unroll
            for (int i = 0; i < 32; i++) a += row[i] * xr[i];
            out[sp] = __float2half_rn(a);
        }
        size_t off = (size_t)kt * SLAB_A + (size_t)(b * 4 + r) * BKH + kk0;
        *reinterpret_cast<uint4*>(&g_Xt[off]) = *reinterpret_cast<const uint4*>(out);
    }
}

// w[o,f,:] -> What, realified [[Wr,Wi],[-Wi,Wr]], into slab layout.
__global__ void xform_w(const float* __restrict__ W) {
    __shared__ float TFs[1024];
    for (int i = threadIdx.x; i < 1024; i += 256) TFs[i] = g_TF[i];
    __syncthreads();

    int t = blockIdx.x * 256 + threadIdx.x;   // 0 .. 16383
    int o = t >> 7, f = t & 127;
    const float* wv = W + (size_t)o * 4096 + f * 32;
    float wr32[32];
#pragma unroll
    for (int q = 0; q < 8; q++) {
        float4 v = *reinterpret_cast<const float4*>(wv + q * 4);
        wr32[q * 4 + 0] = v.x; wr32[q * 4 + 1] = v.y;
        wr32[q * 4 + 2] = v.z; wr32[q * 4 + 3] = v.w;
    }
    int kt = f >> 3, kk0 = (f & 7) * 8;
#pragma unroll
    for (int s = 0; s < 4; s++)
#pragma unroll
        for (int c = 0; c < 4; c++) {
            float wr = 0.f, wi = 0.f;
#pragma unroll
            for (int j = 0; j < 32; j++) {
                wr += TFs[(s * 8 + c * 2 + 0) * 32 + j] * wr32[j];
                wi += TFs[(s * 8 + c * 2 + 1) * 32 + j] * wr32[j];
            }
            int kk = kk0 + s * 2;
            int n0 = o * 8 + c * 2;
            size_t base = (size_t)kt * SLAB_B;
            g_Wt16[base + (size_t)(n0 + 0) * BKH + kk + 0] = __float2half_rn(wr);
            g_Wt16[base + (size_t)(n0 + 0) * BKH + kk + 1] = __float2half_rn(-wi);
            g_Wt16[base + (size_t)(n0 + 1) * BKH + kk + 0] = __float2half_rn(wi);
            g_Wt16[base + (size_t)(n0 + 1) * BKH + kk + 1] = __float2half_rn(wr);
        }
}

// ---------------------------------------------------------------------------
#define BM 128
#define BN 128
#define NST 3
#define LDSD 72                          // smem row stride in HALFS (144 B)
#define STG_H (BM * LDSD)                // 9216 halfs per stage per matrix
#define SMEM_BYTES (NST * 2 * STG_H * 2) // 110592

#define CP_ASYNC16(smaddr, gptr) \
    asm volatile("cp.async.cg.shared.global [%0], [%1], 16;" :: "r"(smaddr), "l"(gptr))

__global__ __launch_bounds__(256, 2)
void gemm_tc_kernel(float* __restrict__ C) {
    extern __shared__ __half smem[];
    __half* As = smem;                    // [NST][BM][LDSD]
    __half* Bs = smem + NST * STG_H;
    uint32_t sAs = (uint32_t)__cvta_generic_to_shared(As);
    uint32_t sBs = (uint32_t)__cvta_generic_to_shared(Bs);

    const int tid  = threadIdx.x;
    const int lane = tid & 31;
    const int wid  = tid >> 5;
    const int warpM = wid >> 2;          // 0..1
    const int warpN = wid & 3;           // 0..3
    const int blockRow = blockIdx.y * BM;
    const int blockCol = blockIdx.x * BN;

#define LOAD_TILE(t, stage) do {                                               \
    const __half* _ga = g_Xt   + (size_t)(t) * SLAB_A + (size_t)blockRow * BKH;\
    const __half* _gb = g_Wt16 + (size_t)(t) * SLAB_B + (size_t)blockCol * BKH;\
    uint32_t _sa = sAs + (uint32_t)((stage) * STG_H) * 2u;                     \
    uint32_t _sb = sBs + (uint32_t)((stage) * STG_H) * 2u;                     \
    _Pragma("unroll")                                                          \
    for (int _i = 0; _i < 4; _i++) {                                           \
        int _j = tid + 256 * _i;                                               \
        CP_ASYNC16(_sa + (uint32_t)(((_j >> 3) * LDSD + (_j & 7) * 8) * 2),    \
                   _ga + (size_t)_j * 8);                                      \
    }                                                                          \
    _Pragma("unroll")                                                          \
    for (int _i = 0; _i < 4; _i++) {                                           \
        int _j = tid + 256 * _i;                                               \
        CP_ASYNC16(_sb + (uint32_t)(((_j >> 3) * LDSD + (_j & 7) * 8) * 2),    \
                   _gb + (size_t)_j * 8);                                      \
    }                                                                          \
    asm volatile("cp.async.commit_group;");                                    \
} while (0)

    float acc[4][4][4] = {};

    LOAD_TILE(0, 0);
    LOAD_TILE(1, 1);

    const int aRowBase = warpM * 64 + (lane >> 2);
    const int t2 = (lane & 3) * 2;
    const int bRowBase = warpN * 32 + (lane >> 2);

    for (int t = 0; t < KT; t++) {       // 16 iterations
        const int stage = t % NST;
        if (t < KT - 1) asm volatile("cp.async.wait_group 1;");
        else            asm volatile("cp.async.wait_group 0;");
        __syncthreads();
        if (t + 2 < KT) LOAD_TILE(t + 2, (t + 2) % NST);

        const __half* as = As + stage * STG_H + aRowBase * LDSD + t2;
        const __half* bs = Bs + stage * STG_H + bRowBase * LDSD + t2;

#pragma unroll
        for (int ks = 0; ks < 4; ks++) {             // four k16 slices in BK=64
            const int kof = ks * 16;
            uint32_t a[4][4], b[4][2];
#pragma unroll
            for (int mf = 0; mf < 4; mf++) {
                a[mf][0] = *reinterpret_cast<const uint32_t*>(&as[(mf * 16    ) * LDSD + kof    ]);
                a[mf][1] = *reinterpret_cast<const uint32_t*>(&as[(mf * 16 + 8) * LDSD + kof    ]);
                a[mf][2] = *reinterpret_cast<const uint32_t*>(&as[(mf * 16    ) * LDSD + kof + 8]);
                a[mf][3] = *reinterpret_cast<const uint32_t*>(&as[(mf * 16 + 8) * LDSD + kof + 8]);
            }
#pragma unroll
            for (int nf = 0; nf < 4; nf++) {
                b[nf][0] = *reinterpret_cast<const uint32_t*>(&bs[(nf * 8) * LDSD + kof    ]);
                b[nf][1] = *reinterpret_cast<const uint32_t*>(&bs[(nf * 8) * LDSD + kof + 8]);
            }
#pragma unroll
            for (int mf = 0; mf < 4; mf++)
#pragma unroll
                for (int nf = 0; nf < 4; nf++)
                    asm volatile(
                        "mma.sync.aligned.m16n8k16.row.col.f32.f16.f16.f32 "
                        "{%0,%1,%2,%3}, {%4,%5,%6,%7}, {%8,%9}, {%0,%1,%2,%3};"
                        : "+f"(acc[mf][nf][0]), "+f"(acc[mf][nf][1]),
                          "+f"(acc[mf][nf][2]), "+f"(acc[mf][nf][3])
                        : "r"(a[mf][0]), "r"(a[mf][1]), "r"(a[mf][2]), "r"(a[mf][3]),
                          "r"(b[nf][0]), "r"(b[nf][1]));
        }
    }

    // ---- fused epilogue, SPILL-FREE ----------------------------------------
    // Stage acc into S[e][g] (e = blade-part index, g = multivector id).
    float* S   = reinterpret_cast<float*>(smem);       // [32][520]
    float* TIs = S + 32 * 520;                         // 1024 floats
    __syncthreads();

    for (int idx = tid; idx < 1024; idx += 256) TIs[idx] = g_TI[idx];

#pragma unroll
    for (int mf = 0; mf < 4; mf++)
#pragma unroll
        for (int nf = 0; nf < 4; nf++)
#pragma unroll
            for (int cc = 0; cc < 4; cc++) {
                int ml = warpM * 64 + mf * 16 + (lane >> 2) + ((cc >> 1) ? 8 : 0);
                int nl = warpN * 32 + nf * 8 + (lane & 3) * 2 + (cc & 1);
                int e = (ml & 3) * 8 + (nl & 7);
                int g = (ml >> 2) * 16 + (nl >> 3);
                S[e * 520 + g] = acc[mf][nf][cc];
            }
    __syncthreads();

    // Per multivector g: norm via TI orthogonality (TI TI^T = I/4 =>
    // sum_i y_i^2 = 0.25 * sum_e v_e^2), then stream outputs with a single
    // scalar accumulator each. No arrays -> no register spills.
    for (int g = tid; g < 512; g += 256) {
        float ssum = 0.f;
#pragma unroll
        for (int e = 0; e < 32; e++) {
            float ve = S[e * 520 + g];
            ssum += ve * ve;
        }
        float inv = rsqrtf(0.25f * ssum + 1e-6f);

        int b_l = g >> 4, o_l = g & 15;
        float* crow = C + ((size_t)(blockIdx.y * 32 + b_l)) * 4096
                        + (size_t)(blockIdx.x * 16 + o_l) * 32;
#pragma unroll
        for (int i4 = 0; i4 < 8; i4++) {
            float o0 = 0.f, o1 = 0.f, o2 = 0.f, o3 = 0.f;
#pragma unroll
            for (int e = 0; e < 32; e++) {
                float ve = S[e * 520 + g];
                o0 += TIs[(i4 * 4 + 0) * 32 + e] * ve;
                o1 += TIs[(i4 * 4 + 1) * 32 + e] * ve;
                o2 += TIs[(i4 * 4 + 2) * 32 + e] * ve;
                o3 += TIs[(i4 * 4 + 3) * 32 + e] * ve;
            }
            float4 o4 = make_float4(o0 * inv, o1 * inv, o2 * inv, o3 * inv);
            *reinterpret_cast<float4*>(crow + i4 * 4) = o4;
        }
    }
}

// ---------------------------------------------------------------------------
extern "C" void kernel_launch(void* const* d_in, const int* in_sizes, int n_in,
                              void* d_out, int out_size) {
    const float* x = (const float*)d_in[0];
    const float* w = (const float*)d_in[1];
    if (n_in >= 2 && in_sizes[0] == 524288 && in_sizes[1] == 16777216) {
        const float* t = x; x = w; w = t;  // defensive order swap
    }
    float* y = (float*)d_out;

    build_tables<<<1, 32>>>();
    xform_x<<<2048, 256>>>(x);
    xform_w<<<64, 256>>>(w);

    cudaFuncSetAttribute(gemm_tc_kernel,
                         cudaFuncAttributeMaxDynamicSharedMemorySize, SMEM_BYTES);
    dim3 grid(GN / BN, GM / BM);  // 8 x 128
    gemm_tc_kernel<<<grid, 256, SMEM_BYTES>>>(y);
}